// round 9
// baseline (speedup 1.0000x reference)
#include <cuda_runtime.h>
#include <cstdint>

#define OUT_F 16

// Monotonic ticket counter for the software global barrier. Never reset:
// each execution adds exactly gridDim.x arrivals, so at kernel boundaries
// the counter is a multiple of gridDim.x and each CTA waits for the next
// multiple. Safe across CUDA-graph replays.
__device__ unsigned g_arrive = 0;

// ---------------------------------------------------------------------------
// Fused: zero output + global barrier + scatter-add (quad layout, 2-way ILP).
// Persistent grid of 1184 CTAs (148 SMs x 8 = FULL 64 warps/SM occupancy,
// residency guaranteed by __launch_bounds__(256,8) which caps regs at 32).
// ---------------------------------------------------------------------------
__global__ void __launch_bounds__(256, 8)
fused_zero_scatter(const int* __restrict__ src,
                   const float4* __restrict__ w,     // edge_w as [4E] float4
                   float* __restrict__ out,          // [N][16]
                   int work,                         // 4*E quad elements
                   int n4)                           // output float4 count
{
    const int tid = blockIdx.x * blockDim.x + threadIdx.x;
    const int S = gridDim.x * blockDim.x;            // 303104

    // ---- phase 1: zero the output (harness poisons it with 0xAA) ----
    float4* o4 = (float4*)out;
    for (int i = tid; i < n4; i += S)
        o4[i] = make_float4(0.f, 0.f, 0.f, 0.f);

    // ---- global barrier: zero-stores visible before any RED lands ----
    __syncthreads();
    __threadfence();                                  // release our stores
    if (threadIdx.x == 0) {
        unsigned ticket = atomicAdd(&g_arrive, 1) + 1;
        unsigned target = ((ticket + gridDim.x - 1) / gridDim.x) * gridDim.x;
        while (*(volatile unsigned*)&g_arrive < target)
            __nanosleep(32);
    }
    __syncthreads();
    __threadfence();                                  // acquire peers' stores

    // ---- phase 2: scatter, 2-way unrolled grid-stride (fits 32-reg cap) ----
    int t = tid;
    for (; t + S < work; t += 2 * S) {
        int ta = t, tb = t + S;

        int sa = __ldg(src + (ta >> 2));
        int sb = __ldg(src + (tb >> 2));
        float4 va = __ldcs(w + ta);
        float4 vb = __ldcs(w + tb);

        float* da = out + (size_t)sa * OUT_F + (ta & 3) * 4;
        asm volatile("red.global.add.v4.f32 [%0], {%1,%2,%3,%4};"
                     :: "l"(da), "f"(va.x), "f"(va.y), "f"(va.z), "f"(va.w) : "memory");
        float* db = out + (size_t)sb * OUT_F + (tb & 3) * 4;
        asm volatile("red.global.add.v4.f32 [%0], {%1,%2,%3,%4};"
                     :: "l"(db), "f"(vb.x), "f"(vb.y), "f"(vb.z), "f"(vb.w) : "memory");
    }
    if (t < work) {
        int s = __ldg(src + (t >> 2));
        float4 v = __ldcs(w + t);
        float* d = out + (size_t)s * OUT_F + (t & 3) * 4;
        asm volatile("red.global.add.v4.f32 [%0], {%1,%2,%3,%4};"
                     :: "l"(d), "f"(v.x), "f"(v.y), "f"(v.z), "f"(v.w) : "memory");
    }
}

// ---------------------------------------------------------------------------
// kernel_launch
// Inputs (metadata order): edge [2, E] int32, edge_w [E, 16] f32, N, E, F
// ---------------------------------------------------------------------------
extern "C" void kernel_launch(void* const* d_in, const int* in_sizes, int n_in,
                              void* d_out, int out_size) {
    const int*    edge   = (const int*)d_in[0];      // [2, E]; row 0 = src
    const float4* edge_w = (const float4*)d_in[1];   // [E, 16] -> [4E] float4
    float*        out    = (float*)d_out;            // [N, 16]

    const int E    = in_sizes[0] / 2;                // edge has 2*E elements
    const int work = 4 * E;                          // quad elements
    const int n4   = out_size / 4;                   // output float4 count

    const int threads = 256;
    const int blocks  = 148 * 8;                     // full occupancy, resident

    fused_zero_scatter<<<blocks, threads>>>(edge, edge_w, out, work, n4);
}

// round 10
// speedup vs baseline: 1.1527x; 1.1527x over previous
#include <cuda_runtime.h>
#include <cstdint>

#define OUT_F 16

// ---------------------------------------------------------------------------
// Scatter-add, quad layout (4 threads per edge, one float4 chunk each) with
// 2-way ILP: each thread handles quad-elements t and t+half, issuing all 4
// loads before the 2 REDs. One-shot (no loop): finished warps are replaced
// by fresh CTAs whose first instructions are loads — CTA replacement acts as
// the software pipeline that keeps DRAM at ~59% while LTS atomics bind.
// Both element streams are fully coalesced (half is a multiple of 32); each
// edge's 4 RED lanes form one contiguous 64B group -> LTS merges internally.
// Best measured configuration: 48.45us scatter (R6).
// ---------------------------------------------------------------------------
__global__ void __launch_bounds__(256)
scatter_add_quad2(const int* __restrict__ src,
                  const float4* __restrict__ w,    // edge_w as [4E] float4
                  float* __restrict__ out,         // [N][16]
                  int work,                        // 4*E
                  int half)                        // >= work/2, multiple of 32
{
    int t = blockIdx.x * blockDim.x + threadIdx.x;
    if (t >= half) return;

    int t2 = t + half;
    bool p2 = (t2 < work);

    // element 1
    int e1 = t >> 2, c1 = t & 3;
    int s1 = __ldg(src + e1);
    float4 v1 = __ldcs(w + t);

    // element 2
    int e2 = t2 >> 2, c2 = t2 & 3;
    int s2 = p2 ? __ldg(src + e2) : 0;
    float4 v2 = p2 ? __ldcs(w + t2) : make_float4(0.f, 0.f, 0.f, 0.f);

    float* dst1 = out + (size_t)s1 * OUT_F + c1 * 4;
    asm volatile("red.global.add.v4.f32 [%0], {%1,%2,%3,%4};"
                 :: "l"(dst1), "f"(v1.x), "f"(v1.y), "f"(v1.z), "f"(v1.w)
                 : "memory");

    if (p2) {
        float* dst2 = out + (size_t)s2 * OUT_F + c2 * 4;
        asm volatile("red.global.add.v4.f32 [%0], {%1,%2,%3,%4};"
                     :: "l"(dst2), "f"(v2.x), "f"(v2.y), "f"(v2.z), "f"(v2.w)
                     : "memory");
    }
}

// ---------------------------------------------------------------------------
// kernel_launch
// Inputs (metadata order): edge [2, E] int32, edge_w [E, 16] f32, N, E, F
// Zero via memset graph node (cheapest measured: 2.75us incl. node overhead
// vs 4.1us for a zeroing kernel launch).
// ---------------------------------------------------------------------------
extern "C" void kernel_launch(void* const* d_in, const int* in_sizes, int n_in,
                              void* d_out, int out_size) {
    const int*    edge   = (const int*)d_in[0];      // [2, E]; row 0 = src
    const float4* edge_w = (const float4*)d_in[1];   // [E, 16] -> [4E] float4
    float*        out    = (float*)d_out;            // [N, 16]

    const int E    = in_sizes[0] / 2;                // edge has 2*E elements
    const int work = 4 * E;                          // quad elements

    int half = (work + 1) / 2;
    half = (half + 31) & ~31;                        // warp-aligned 2nd stream

    cudaMemsetAsync(d_out, 0, (size_t)out_size * sizeof(float));

    {
        int threads = 256;
        int blocks = (half + threads - 1) / threads; // 25000 for E=3.2M
        scatter_add_quad2<<<blocks, threads>>>(edge, edge_w, out, work, half);
    }
}